// round 1
// baseline (speedup 1.0000x reference)
#include <cuda_runtime.h>

// out[b, p, d] = x[b, p] * W[p, d] + bias[p, d]
// B=64, P=2000, D=512 (fp32). HBM-write-bound: 262MB out, 8.5MB in.
// One thread per (p, d4) float4 column-chunk; W/b live in registers and are
// reused across all 64 batch rows. Streaming stores (.cs) for the output.

#define B_DIM 64
#define P_DIM 2000
#define D_DIM 512
#define D4 (D_DIM / 4)          // 128
#define PD4 (P_DIM * D4)        // 256000

__global__ __launch_bounds__(256) void feature_expander_kernel(
    const float* __restrict__ x,      // [B, P]
    const float4* __restrict__ W,     // [P, D/4]
    const float4* __restrict__ bias,  // [P, D/4]
    float4* __restrict__ out)         // [B, P, D/4]
{
    int idx = blockIdx.x * blockDim.x + threadIdx.x;
    if (idx >= PD4) return;

    int p = idx / D4;

    float4 w = __ldg(&W[idx]);
    float4 bv = __ldg(&bias[idx]);

    const float* xp = x + p;          // x[b*P + p]
    float4* op = out + idx;           // out[b*PD4 + idx]

    #pragma unroll 8
    for (int b = 0; b < B_DIM; b++) {
        float xv = __ldg(xp + b * P_DIM);
        float4 o;
        o.x = fmaf(xv, w.x, bv.x);
        o.y = fmaf(xv, w.y, bv.y);
        o.z = fmaf(xv, w.z, bv.z);
        o.w = fmaf(xv, w.w, bv.w);
        __stcs(op + b * PD4, o);      // streaming store: bypass L2 persistence
    }
}

extern "C" void kernel_launch(void* const* d_in, const int* in_sizes, int n_in,
                              void* d_out, int out_size) {
    const float*  x  = (const float*)d_in[0];
    const float4* W  = (const float4*)d_in[1];
    const float4* bb = (const float4*)d_in[2];
    float4* out = (float4*)d_out;

    int threads = 256;
    int blocks = (PD4 + threads - 1) / threads;  // 1000
    feature_expander_kernel<<<blocks, threads>>>(x, W, bb, out);
}

// round 2
// speedup vs baseline: 1.0671x; 1.0671x over previous
#include <cuda_runtime.h>

// out[b, p, d] = x[b, p] * W[p, d] + bias[p, d]
// B=64, P=2000, D=512 (fp32). HBM-write-bound: 262MB out.
// Thread = one (p, d4) float4 column-chunk x 16 batch rows.
// grid.y splits the 64 batches into 4 chunks of 16 -> 4000 blocks total,
// reducing wave-quantization tail (1000 blocks = 6.76 waves -> 4000 = 27 waves).
// W/b loaded once per thread (L2-resident after first wave), streaming stores.

#define B_DIM 64
#define P_DIM 2000
#define D_DIM 512
#define D4 (D_DIM / 4)          // 128
#define PD4 (P_DIM * D4)        // 256000
#define B_CHUNK 16              // batches per thread
#define N_CHUNKS (B_DIM / B_CHUNK)  // 4

__global__ __launch_bounds__(256) void feature_expander_kernel(
    const float* __restrict__ x,      // [B, P]
    const float4* __restrict__ W,     // [P, D/4]
    const float4* __restrict__ bias,  // [P, D/4]
    float4* __restrict__ out)         // [B, P, D/4]
{
    int idx = blockIdx.x * blockDim.x + threadIdx.x;
    if (idx >= PD4) return;

    int p = idx / D4;
    int b0 = blockIdx.y * B_CHUNK;

    float4 w = __ldg(&W[idx]);
    float4 bv = __ldg(&bias[idx]);

    const float* xp = x + b0 * P_DIM + p;   // x[(b0+i)*P + p]
    float4* op = out + (size_t)b0 * PD4 + idx;

    #pragma unroll
    for (int i = 0; i < B_CHUNK; i++) {
        float xv = __ldg(xp + i * P_DIM);
        float4 o;
        o.x = fmaf(xv, w.x, bv.x);
        o.y = fmaf(xv, w.y, bv.y);
        o.z = fmaf(xv, w.z, bv.z);
        o.w = fmaf(xv, w.w, bv.w);
        __stcs(op + (size_t)i * PD4, o);    // streaming store
    }
}

extern "C" void kernel_launch(void* const* d_in, const int* in_sizes, int n_in,
                              void* d_out, int out_size) {
    const float*  x  = (const float*)d_in[0];
    const float4* W  = (const float4*)d_in[1];
    const float4* bb = (const float4*)d_in[2];
    float4* out = (float4*)d_out;

    dim3 grid((PD4 + 255) / 256, N_CHUNKS);  // 1000 x 4
    feature_expander_kernel<<<grid, 256>>>(x, W, bb, out);
}

// round 3
// speedup vs baseline: 1.0935x; 1.0248x over previous
#include <cuda_runtime.h>

// out[b, p, d] = x[b, p] * W[p, d] + bias[p, d]
// B=64, P=2000, D=512 (fp32). HBM-write-bound: 262MB out (~6.5TB/s achieved).
// Thread = one (p, d4) float4 column-chunk x 8 batch rows.
// grid.y splits 64 batches into 8 chunks of 8 -> 8000 blocks (54 waves),
// minimizing wave-quantization tail and register pressure (higher occupancy
// to cover the STG.128 LSU issue cost). W/b are L2-resident; streaming stores
// keep the 262MB output from evicting them.

#define B_DIM 64
#define P_DIM 2000
#define D_DIM 512
#define D4 (D_DIM / 4)          // 128
#define PD4 (P_DIM * D4)        // 256000
#define B_CHUNK 8               // batches per thread
#define N_CHUNKS (B_DIM / B_CHUNK)  // 8

__global__ __launch_bounds__(256) void feature_expander_kernel(
    const float* __restrict__ x,      // [B, P]
    const float4* __restrict__ W,     // [P, D/4]
    const float4* __restrict__ bias,  // [P, D/4]
    float4* __restrict__ out)         // [B, P, D/4]
{
    int idx = blockIdx.x * blockDim.x + threadIdx.x;
    if (idx >= PD4) return;

    int p = idx / D4;
    int b0 = blockIdx.y * B_CHUNK;

    float4 w = __ldg(&W[idx]);
    float4 bv = __ldg(&bias[idx]);

    const float* xp = x + b0 * P_DIM + p;       // x[(b0+i)*P + p]
    float4* op = out + (size_t)b0 * PD4 + idx;

    #pragma unroll
    for (int i = 0; i < B_CHUNK; i++) {
        float xv = __ldg(xp + i * P_DIM);
        float4 o;
        o.x = fmaf(xv, w.x, bv.x);
        o.y = fmaf(xv, w.y, bv.y);
        o.z = fmaf(xv, w.z, bv.z);
        o.w = fmaf(xv, w.w, bv.w);
        __stcs(op + (size_t)i * PD4, o);        // streaming store
    }
}

extern "C" void kernel_launch(void* const* d_in, const int* in_sizes, int n_in,
                              void* d_out, int out_size) {
    const float*  x  = (const float*)d_in[0];
    const float4* W  = (const float4*)d_in[1];
    const float4* bb = (const float4*)d_in[2];
    float4* out = (float4*)d_out;

    dim3 grid((PD4 + 255) / 256, N_CHUNKS);  // 1000 x 8
    feature_expander_kernel<<<grid, 256>>>(x, W, bb, out);
}